// round 6
// baseline (speedup 1.0000x reference)
#include <cuda_runtime.h>

// Tensor: (1024, 1024, 3, 3) fp32
#define OC_N    1024
#define IC_N    1024
#define ROWS_N  (OC_N * IC_N)        // 1048576 kernel rows of 9
#define N_TOT   (ROWS_N * 9)         // 9437184
#define N_VEC4  (N_TOT / 4)          // 2359296
#define MAX_GRID 1152                // 1152*256 threads * 8 float4 = N_VEC4 exactly

__device__ float    g_part_max[MAX_GRID];
__device__ float    g_part_resid[ROWS_N / 256];   // 4096 block partials
__device__ unsigned g_row_cand[ROWS_N];           // 4 MB, 32-bit keys

// ---------------------------------------------------------------------------
// Pass A: per-block max|t| partials (no atomics, no init kernel needed).
__global__ void __launch_bounds__(256) k_maxabs(const float4* __restrict__ in) {
    const int base = blockIdx.x * 256 + threadIdx.x;
    const int stride = MAX_GRID * 256;
    float m = 0.0f;
#pragma unroll
    for (int k = 0; k < 8; k++) {
        float4 v = in[base + k * stride];
        m = fmaxf(m, fmaxf(fmaxf(fabsf(v.x), fabsf(v.y)),
                           fmaxf(fabsf(v.z), fabsf(v.w))));
    }
#pragma unroll
    for (int o = 16; o > 0; o >>= 1)
        m = fmaxf(m, __shfl_xor_sync(0xFFFFFFFFu, m, o));
    __shared__ float sm[8];
    if ((threadIdx.x & 31) == 0) sm[threadIdx.x >> 5] = m;
    __syncthreads();
    if (threadIdx.x == 0) {
        m = sm[0];
#pragma unroll
        for (int i = 1; i < 8; i++) m = fmaxf(m, sm[i]);
        g_part_max[blockIdx.x] = m;
    }
}

// ---------------------------------------------------------------------------
// Per-block scale: reduce the 1152 partial maxima (hot in L2) identically in
// every block of both consumer kernels -> bit-identical scale everywhere.
// Must be called by all 256 threads (contains __syncthreads).
__device__ __forceinline__ float block_scale_256(float* swarp /*shared[8]*/) {
    float m = 0.0f;
    for (int i = threadIdx.x; i < MAX_GRID; i += 256)
        m = fmaxf(m, g_part_max[i]);
#pragma unroll
    for (int o = 16; o > 0; o >>= 1)
        m = fmaxf(m, __shfl_xor_sync(0xFFFFFFFFu, m, o));
    if ((threadIdx.x & 31) == 0) swarp[threadIdx.x >> 5] = m;
    __syncthreads();
    float mm = swarp[0];
#pragma unroll
    for (int i = 1; i < 8; i++) mm = fmaxf(mm, swarp[i]);
    return __fdiv_rn(mm, 127.0f);          // IEEE RN, uniform in block
}

// ---------------------------------------------------------------------------
// Pass B: per kernel-row (9 elems) SQuant stage.
__global__ void __launch_bounds__(256) k_rows(const float* __restrict__ in,
                                              float* __restrict__ out) {
    __shared__ __align__(16) float tile[2304];  // 9216 B
    __shared__ float swscale[8];
    __shared__ float swred[8];

    const float4* in4 = reinterpret_cast<const float4*>(in)
                        + (size_t)blockIdx.x * 576;
    float4* t4 = reinterpret_cast<float4*>(tile);
#pragma unroll
    for (int i = threadIdx.x; i < 576; i += 256) t4[i] = in4[i];

    // (block_scale_256's __syncthreads also covers the tile stores above)
    const float scl = block_scale_256(swscale);
    const float rcp = __frcp_rn(scl);

    // gcd(9,32)=1 -> thread*9+i is bank-conflict-free across a warp.
    float rn[9], re[9], p[9];
    float esum = 0.0f;
#pragma unroll
    for (int i = 0; i < 9; i++) {
        float t  = tile[threadIdx.x * 9 + i];
        float q0 = __fmul_rn(t, rcp);                          // Markstein div:
        float x  = __fmaf_rn(__fmaf_rn(-scl, q0, t), rcp, q0); // == t/scl (RN)
        x = fminf(fmaxf(x, -127.0f), 127.0f);
        float r = rintf(x);           // round-half-to-even == jnp.round
        rn[i] = r;
        re[i] = __fadd_rn(r, -x);
        esum  = __fadd_rn(esum, re[i]);
    }

    const int   nf = (int)rintf(fabsf(esum));
    const bool  up = (esum < 0.0f);
    const float d1 = up ? 1.0f : -1.0f;
#pragma unroll
    for (int i = 0; i < 9; i++) {
        float c = up ? -re[i] : re[i];   // candidate iff re has right sign
        p[i] = fmaxf(c, 0.0f);
    }

    // Pairwise stable rank: tie (==) -> lower index outranks.
    int rank[9];
#pragma unroll
    for (int j = 0; j < 9; j++) rank[j] = j;
#pragma unroll
    for (int i = 0; i < 8; i++)
#pragma unroll
        for (int j = i + 1; j < 9; j++) {
            int g = (int)(p[j] > p[i]);
            rank[i] += g;
            rank[j] -= g;
        }

    // Flips: exactly nf flipped (nf <= #candidates holds in stage 1).
    int bi = -1;
#pragma unroll
    for (int i = 0; i < 9; i++) {
        if (rank[i] < nf)      rn[i] += d1;
        if (rank[i] == nf - 1) bi = i;          // boundary element
        tile[threadIdx.x * 9 + i] = rn[i];      // own slots only: no hazard
    }
    float resid = __fmaf_rn((float)nf, d1, esum);

    // 32-bit candidate key: dir(1) | prio17 | (9216-idx)(14).
    // |re2| in [0.5, 1) -> exponent fixed at 126; mantissa alone orders it.
    unsigned cand = 0u;
    const int row = blockIdx.x * 256 + threadIdx.x;
    if (bi >= 0) {
        float re2 = __fadd_rn(re[bi], d1);
        int elemFlat = (row & (IC_N - 1)) * 9 + bi;
        unsigned mant = __float_as_uint(fabsf(re2)) & 0x7FFFFFu;
        cand = ((up ? 1u : 0u) << 31) | ((mant >> 6) << 14)
             | (unsigned)(9216 - elemFlat);
    }
    g_row_cand[row] = cand;

    // block-reduce residual -> one partial per 256 rows
#pragma unroll
    for (int o = 16; o > 0; o >>= 1)
        resid += __shfl_xor_sync(0xFFFFFFFFu, resid, o);
    if ((threadIdx.x & 31) == 0) swred[threadIdx.x >> 5] = resid;
    __syncthreads();
    if (threadIdx.x == 0) {
        float s = swred[0];
#pragma unroll
        for (int i = 1; i < 8; i++) s += swred[i];
        g_part_resid[blockIdx.x] = s;
    }

    float4* out4 = reinterpret_cast<float4*>(out) + (size_t)blockIdx.x * 576;
#pragma unroll
    for (int i = threadIdx.x; i < 576; i += 256) {
        float4 v = t4[i];
        v.x = __fmul_rn(v.x, scl); v.y = __fmul_rn(v.y, scl);
        v.z = __fmul_rn(v.z, scl); v.w = __fmul_rn(v.w, scl);
        out4[i] = v;
    }
}

// ---------------------------------------------------------------------------
// Pass C: one WARP per OC channel. Patches are disjoint +/-scale adds, so
// only the SET of top-nf keys matters (order-free). Histogram selection:
//   1. 256-bucket smem histogram on key top-8-bits (one-shot, parallel)
//   2. warp suffix-scan finds threshold bucket B and c1 = #keys above it
//   3. keys in buckets > B: patch immediately (unordered, MLP-overlapped)
//   4. bucket B: serial pick loop for only k2 = nf - c1 picks (expected 1-4)
__global__ void __launch_bounds__(256) k_channel(float* __restrict__ out) {
    __shared__ unsigned shist[8][256];
    __shared__ unsigned spatch[8][512];
    __shared__ float    swscale[8];

    const float scale = block_scale_256(swscale);   // all 256 threads

    const int wslot = threadIdx.x >> 5;
    const int oc    = (blockIdx.x << 3) | wslot;
    const int lane  = threadIdx.x & 31;

    const int pb = oc << 2;
    const float esum = ((g_part_resid[pb] + g_part_resid[pb + 1])
                      + g_part_resid[pb + 2]) + g_part_resid[pb + 3];
    const int nf = (int)rintf(fabsf(esum));
    if (nf == 0) return;
    const bool upc = (esum < 0.0f);
    // stage-2 up-flip reverts a stage-1 DOWN-flipped boundary (dir bit 0)
    const unsigned want  = upc ? 0u : 1u;
    const float    delta = upc ? scale : -scale;

    // Load 1024 keys as uint4 (coalesced), filter by direction.
    const uint4* kp = reinterpret_cast<const uint4*>(g_row_cand)
                      + ((size_t)oc << 8);
    unsigned key[32];
#pragma unroll
    for (int j = 0; j < 8; j++) {
        uint4 v = kp[j * 32 + lane];
        key[j*4+0] = (v.x != 0u && (v.x >> 31) == want) ? (v.x & 0x7FFFFFFFu) : 0u;
        key[j*4+1] = (v.y != 0u && (v.y >> 31) == want) ? (v.y & 0x7FFFFFFFu) : 0u;
        key[j*4+2] = (v.z != 0u && (v.z >> 31) == want) ? (v.z & 0x7FFFFFFFu) : 0u;
        key[j*4+3] = (v.w != 0u && (v.w >> 31) == want) ? (v.w & 0x7FFFFFFFu) : 0u;
    }

    // --- 1. histogram on top 8 bits (genuine keys only; key!=0) ---
    unsigned* const h = shist[wslot];
#pragma unroll
    for (int i = lane; i < 256; i += 32) h[i] = 0u;
    __syncwarp();
#pragma unroll
    for (int j = 0; j < 32; j++)
        if (key[j] != 0u) atomicAdd(&h[key[j] >> 23], 1u);
    __syncwarp();

    // --- 2. suffix scan: lane l owns group g=31-l (buckets 8g..8g+7) ---
    const int g = 31 - lane;
    unsigned s = 0u;
#pragma unroll
    for (int b = 0; b < 8; b++) s += h[g * 8 + b];
    unsigned C = s;                       // inclusive prefix over lanes
#pragma unroll
    for (int o = 1; o < 32; o <<= 1) {
        unsigned v = __shfl_up_sync(0xFFFFFFFFu, C, o);
        if (lane >= o) C += v;
    }
    const unsigned ball = __ballot_sync(0xFFFFFFFFu, C >= (unsigned)nf);
    const int lsel = (ball == 0u) ? 31 : (__ffs(ball) - 1);
    const unsigned Cl = __shfl_sync(0xFFFFFFFFu, C, lsel);
    const unsigned sl = __shfl_sync(0xFFFFFFFFu, s, lsel);
    const int gsel = 31 - lsel;
    // walk buckets within the group from the top (uniform, broadcast LDS)
    unsigned hb[8];
#pragma unroll
    for (int b = 0; b < 8; b++) hb[b] = h[gsel * 8 + b];
    int B = gsel * 8;
    unsigned c1 = Cl - sl;                // count in buckets above group
    bool found = false;
#pragma unroll
    for (int b = 7; b >= 1; b--) {
        if (!found) {
            if (c1 + hb[b] >= (unsigned)nf) { B = gsel * 8 + b; found = true; }
            else c1 += hb[b];
        }
    }

    // --- 3. patch all keys in buckets > B; keep only bucket-B keys ---
    float* const ochan = out + (size_t)oc * 9216;
#pragma unroll
    for (int j = 0; j < 32; j++) {
        const unsigned kb = key[j] >> 23;
        if (key[j] != 0u && kb > (unsigned)B)
            ochan[9216 - (int)(key[j] & 0x3FFFu)] += delta;
        key[j] = (key[j] != 0u && kb == (unsigned)B) ? key[j] : 0u;
    }

    // --- 4. serial pick loop for the remaining k2 picks (tiny) ---
    const int k2 = nf - (int)c1;          // >= 1
    unsigned lmax;
    {
        unsigned t[32];
#pragma unroll
        for (int j = 0; j < 32; j++) t[j] = key[j];
#pragma unroll
        for (int st = 16; st > 0; st >>= 1)
#pragma unroll
            for (int j = 0; j < 16; j++)
                if (j < st) t[j] = umax(t[j], t[j + st]);
        lmax = t[0];
    }
    unsigned* const patch = spatch[wslot];
    int npick = 0;
    for (int it = 0; it < k2; it++) {
        const unsigned m = __reduce_max_sync(0xFFFFFFFFu, lmax);
        if (m == 0u) break;               // candidates exhausted (safe clamp)
        patch[npick++] = m;               // all lanes, same value: broadcast STS
        unsigned t[32];
#pragma unroll
        for (int j = 0; j < 32; j++) t[j] = (key[j] < m) ? key[j] : 0u;
#pragma unroll
        for (int st = 16; st > 0; st >>= 1)
#pragma unroll
            for (int j = 0; j < 16; j++)
                if (j < st) t[j] = umax(t[j], t[j + st]);
        lmax = t[0];
    }
    __syncwarp();
    for (int i = lane; i < npick; i += 32) {
        const int elemFlat = 9216 - (int)(patch[i] & 0x3FFFu);
        ochan[elemFlat] += delta;         // disjoint addresses, overlapped
    }
}

// ---------------------------------------------------------------------------
extern "C" void kernel_launch(void* const* d_in, const int* in_sizes, int n_in,
                              void* d_out, int out_size) {
    const float* in  = (const float*)d_in[0];
    float*       out = (float*)d_out;

    k_maxabs<<<MAX_GRID, 256>>>((const float4*)in);
    k_rows<<<ROWS_N / 256, 256>>>(in, out);
    k_channel<<<OC_N / 8, 256>>>(out);
}

// round 7
// speedup vs baseline: 1.1739x; 1.1739x over previous
#include <cuda_runtime.h>

// Tensor: (1024, 1024, 3, 3) fp32
#define OC_N    1024
#define IC_N    1024
#define ROWS_N  (OC_N * IC_N)        // 1048576 kernel rows of 9
#define N_TOT   (ROWS_N * 9)         // 9437184
#define N_VEC4  (N_TOT / 4)          // 2359296
#define MAX_GRID 1152                // 1152*256 threads * 8 float4 = N_VEC4 exactly

__device__ float    g_part_max[MAX_GRID];
__device__ float    g_scale;
__device__ float    g_rcp;
__device__ float    g_part_resid[ROWS_N / 256];   // 4096 block partials
__device__ unsigned g_row_cand[ROWS_N];           // 4 MB, 32-bit keys

// ---------------------------------------------------------------------------
// Pass A: per-block max|t| partials (no atomics, no init kernel needed).
__global__ void __launch_bounds__(256) k_maxabs(const float4* __restrict__ in) {
    const int base = blockIdx.x * 256 + threadIdx.x;
    const int stride = MAX_GRID * 256;
    float m = 0.0f;
#pragma unroll
    for (int k = 0; k < 8; k++) {
        float4 v = in[base + k * stride];
        m = fmaxf(m, fmaxf(fmaxf(fabsf(v.x), fabsf(v.y)),
                           fmaxf(fabsf(v.z), fabsf(v.w))));
    }
#pragma unroll
    for (int o = 16; o > 0; o >>= 1)
        m = fmaxf(m, __shfl_xor_sync(0xFFFFFFFFu, m, o));
    __shared__ float sm[8];
    if ((threadIdx.x & 31) == 0) sm[threadIdx.x >> 5] = m;
    __syncthreads();
    if (threadIdx.x == 0) {
        m = sm[0];
#pragma unroll
        for (int i = 1; i < 8; i++) m = fmaxf(m, sm[i]);
        g_part_max[blockIdx.x] = m;
    }
}

// ---------------------------------------------------------------------------
// Final max reduce + scale = max/127 (IEEE) + correctly-rounded reciprocal.
__global__ void __launch_bounds__(128) k_prep() {
    float m = 0.0f;
    for (int i = threadIdx.x; i < MAX_GRID; i += 128)
        m = fmaxf(m, g_part_max[i]);
#pragma unroll
    for (int o = 16; o > 0; o >>= 1)
        m = fmaxf(m, __shfl_xor_sync(0xFFFFFFFFu, m, o));
    __shared__ float sm[4];
    if ((threadIdx.x & 31) == 0) sm[threadIdx.x >> 5] = m;
    __syncthreads();
    if (threadIdx.x == 0) {
        m = fmaxf(fmaxf(sm[0], sm[1]), fmaxf(sm[2], sm[3]));
        float s = __fdiv_rn(m, 127.0f);
        g_scale  = s;
        g_rcp    = __frcp_rn(s);
    }
}

// ---------------------------------------------------------------------------
// Pass B: per kernel-row (9 elems) SQuant stage.
__global__ void __launch_bounds__(256) k_rows(const float* __restrict__ in,
                                              float* __restrict__ out) {
    __shared__ __align__(16) float tile[2304];  // 9216 B
    __shared__ float swred[8];

    const float scl = g_scale;               // broadcast LDG, issued early
    const float rcp = g_rcp;

    const float4* in4 = reinterpret_cast<const float4*>(in)
                        + (size_t)blockIdx.x * 576;
    float4* t4 = reinterpret_cast<float4*>(tile);
#pragma unroll
    for (int i = threadIdx.x; i < 576; i += 256) t4[i] = in4[i];
    __syncthreads();

    // gcd(9,32)=1 -> thread*9+i is bank-conflict-free across a warp.
    float rn[9], re[9], p[9];
    float esum = 0.0f;
#pragma unroll
    for (int i = 0; i < 9; i++) {
        float t  = tile[threadIdx.x * 9 + i];
        float q0 = __fmul_rn(t, rcp);                          // Markstein div:
        float x  = __fmaf_rn(__fmaf_rn(-scl, q0, t), rcp, q0); // == t/scl (RN)
        x = fminf(fmaxf(x, -127.0f), 127.0f);
        float r = rintf(x);           // round-half-to-even == jnp.round
        rn[i] = r;
        re[i] = __fadd_rn(r, -x);
        esum  = __fadd_rn(esum, re[i]);
    }

    const int   nf = (int)rintf(fabsf(esum));
    const bool  up = (esum < 0.0f);
    const float d1 = up ? 1.0f : -1.0f;
#pragma unroll
    for (int i = 0; i < 9; i++) {
        float c = up ? -re[i] : re[i];   // candidate iff re has right sign
        p[i] = fmaxf(c, 0.0f);
    }

    // Pairwise stable rank: tie (==) -> lower index outranks.
    int rank[9];
#pragma unroll
    for (int j = 0; j < 9; j++) rank[j] = j;
#pragma unroll
    for (int i = 0; i < 8; i++)
#pragma unroll
        for (int j = i + 1; j < 9; j++) {
            int g = (int)(p[j] > p[i]);
            rank[i] += g;
            rank[j] -= g;
        }

    // Flips: exactly nf flipped (nf <= #candidates holds in stage 1).
    int bi = -1;
#pragma unroll
    for (int i = 0; i < 9; i++) {
        if (rank[i] < nf)      rn[i] += d1;
        if (rank[i] == nf - 1) bi = i;          // boundary element
        tile[threadIdx.x * 9 + i] = rn[i];      // own slots only: no hazard
    }
    float resid = __fmaf_rn((float)nf, d1, esum);

    // 32-bit candidate key: dir(1) | prio17 | (9216-idx)(14).
    // |re2| in [0.5, 1) -> exponent fixed at 126; mantissa alone orders it.
    unsigned cand = 0u;
    const int row = blockIdx.x * 256 + threadIdx.x;
    if (bi >= 0) {
        float re2 = __fadd_rn(re[bi], d1);
        int elemFlat = (row & (IC_N - 1)) * 9 + bi;
        unsigned mant = __float_as_uint(fabsf(re2)) & 0x7FFFFFu;
        cand = ((up ? 1u : 0u) << 31) | ((mant >> 6) << 14)
             | (unsigned)(9216 - elemFlat);
    }
    g_row_cand[row] = cand;

    // block-reduce residual -> one partial per 256 rows
#pragma unroll
    for (int o = 16; o > 0; o >>= 1)
        resid += __shfl_xor_sync(0xFFFFFFFFu, resid, o);
    if ((threadIdx.x & 31) == 0) swred[threadIdx.x >> 5] = resid;
    __syncthreads();
    if (threadIdx.x == 0) {
        float s = swred[0];
#pragma unroll
        for (int i = 1; i < 8; i++) s += swred[i];
        g_part_resid[blockIdx.x] = s;
    }

    float4* out4 = reinterpret_cast<float4*>(out) + (size_t)blockIdx.x * 576;
#pragma unroll
    for (int i = threadIdx.x; i < 576; i += 256) {
        float4 v = t4[i];
        v.x = __fmul_rn(v.x, scl); v.y = __fmul_rn(v.y, scl);
        v.z = __fmul_rn(v.z, scl); v.w = __fmul_rn(v.w, scl);
        out4[i] = v;
    }
}

// ---------------------------------------------------------------------------
// Pass C: one WARP per OC channel. Patches are disjoint +/-scale adds, so
// only the SET of top-nf keys matters (order-free). Histogram selection:
//   1. 256-bucket smem histogram on key top-8-bits (one-shot, parallel)
//   2. warp suffix-scan finds threshold bucket B and c1 = #keys above it
//   3. keys in buckets > B: patch immediately (unordered, MLP-overlapped)
//   4. bucket B: serial pick loop for only k2 = nf - c1 picks (expected 1-4)
__global__ void __launch_bounds__(256) k_channel(float* __restrict__ out) {
    __shared__ unsigned shist[8][256];
    __shared__ unsigned spatch[8][512];

    const int wslot = threadIdx.x >> 5;
    const int oc    = (blockIdx.x << 3) | wslot;
    const int lane  = threadIdx.x & 31;

    const int pb = oc << 2;
    const float esum = ((g_part_resid[pb] + g_part_resid[pb + 1])
                      + g_part_resid[pb + 2]) + g_part_resid[pb + 3];
    const int nf = (int)rintf(fabsf(esum));
    if (nf == 0) return;
    const bool upc = (esum < 0.0f);
    // stage-2 up-flip reverts a stage-1 DOWN-flipped boundary (dir bit 0)
    const unsigned want  = upc ? 0u : 1u;
    const float    delta = upc ? g_scale : -g_scale;

    // Load 1024 keys as uint4 (coalesced), filter by direction.
    const uint4* kp = reinterpret_cast<const uint4*>(g_row_cand)
                      + ((size_t)oc << 8);
    unsigned key[32];
#pragma unroll
    for (int j = 0; j < 8; j++) {
        uint4 v = kp[j * 32 + lane];
        key[j*4+0] = (v.x != 0u && (v.x >> 31) == want) ? (v.x & 0x7FFFFFFFu) : 0u;
        key[j*4+1] = (v.y != 0u && (v.y >> 31) == want) ? (v.y & 0x7FFFFFFFu) : 0u;
        key[j*4+2] = (v.z != 0u && (v.z >> 31) == want) ? (v.z & 0x7FFFFFFFu) : 0u;
        key[j*4+3] = (v.w != 0u && (v.w >> 31) == want) ? (v.w & 0x7FFFFFFFu) : 0u;
    }

    // --- 1. histogram on top 8 bits (genuine keys only; key!=0) ---
    unsigned* const h = shist[wslot];
#pragma unroll
    for (int i = lane; i < 256; i += 32) h[i] = 0u;
    __syncwarp();
#pragma unroll
    for (int j = 0; j < 32; j++)
        if (key[j] != 0u) atomicAdd(&h[key[j] >> 23], 1u);
    __syncwarp();

    // --- 2. suffix scan: lane l owns group g=31-l (buckets 8g..8g+7) ---
    const int g = 31 - lane;
    unsigned s = 0u;
#pragma unroll
    for (int b = 0; b < 8; b++) s += h[g * 8 + b];
    unsigned C = s;                       // inclusive prefix over lanes
#pragma unroll
    for (int o = 1; o < 32; o <<= 1) {
        unsigned v = __shfl_up_sync(0xFFFFFFFFu, C, o);
        if (lane >= o) C += v;
    }
    const unsigned ball = __ballot_sync(0xFFFFFFFFu, C >= (unsigned)nf);
    const int lsel = (ball == 0u) ? 31 : (__ffs(ball) - 1);
    const unsigned Cl = __shfl_sync(0xFFFFFFFFu, C, lsel);
    const unsigned sl = __shfl_sync(0xFFFFFFFFu, s, lsel);
    const int gsel = 31 - lsel;
    // walk buckets within the group from the top (uniform, broadcast LDS)
    unsigned hb[8];
#pragma unroll
    for (int b = 0; b < 8; b++) hb[b] = h[gsel * 8 + b];
    int B = gsel * 8;
    unsigned c1 = Cl - sl;                // count in buckets above group
    bool found = false;
#pragma unroll
    for (int b = 7; b >= 1; b--) {
        if (!found) {
            if (c1 + hb[b] >= (unsigned)nf) { B = gsel * 8 + b; found = true; }
            else c1 += hb[b];
        }
    }

    // --- 3. patch all keys in buckets > B; keep only bucket-B keys ---
    float* const ochan = out + (size_t)oc * 9216;
#pragma unroll
    for (int j = 0; j < 32; j++) {
        const unsigned kb = key[j] >> 23;
        if (key[j] != 0u && kb > (unsigned)B)
            ochan[9216 - (int)(key[j] & 0x3FFFu)] += delta;
        key[j] = (key[j] != 0u && kb == (unsigned)B) ? key[j] : 0u;
    }

    // --- 4. serial pick loop for the remaining k2 picks (tiny) ---
    const int k2 = nf - (int)c1;          // >= 1
    unsigned lmax;
    {
        unsigned t[32];
#pragma unroll
        for (int j = 0; j < 32; j++) t[j] = key[j];
#pragma unroll
        for (int st = 16; st > 0; st >>= 1)
#pragma unroll
            for (int j = 0; j < 16; j++)
                if (j < st) t[j] = umax(t[j], t[j + st]);
        lmax = t[0];
    }
    unsigned* const patch = spatch[wslot];
    int npick = 0;
    for (int it = 0; it < k2; it++) {
        const unsigned m = __reduce_max_sync(0xFFFFFFFFu, lmax);
        if (m == 0u) break;               // candidates exhausted (safe clamp)
        if (lane == 0) patch[npick] = m;  // STS only: off the critical path
        npick++;
        unsigned t[32];
#pragma unroll
        for (int j = 0; j < 32; j++) t[j] = (key[j] < m) ? key[j] : 0u;
#pragma unroll
        for (int st = 16; st > 0; st >>= 1)
#pragma unroll
            for (int j = 0; j < 16; j++)
                if (j < st) t[j] = umax(t[j], t[j + st]);
        lmax = t[0];
    }
    __syncwarp();
    for (int i = lane; i < npick; i += 32) {
        const int elemFlat = 9216 - (int)(patch[i] & 0x3FFFu);
        ochan[elemFlat] += delta;         // disjoint addresses, overlapped
    }
}

// ---------------------------------------------------------------------------
extern "C" void kernel_launch(void* const* d_in, const int* in_sizes, int n_in,
                              void* d_out, int out_size) {
    const float* in  = (const float*)d_in[0];
    float*       out = (float*)d_out;

    k_maxabs<<<MAX_GRID, 256>>>((const float4*)in);
    k_prep<<<1, 128>>>();
    k_rows<<<ROWS_N / 256, 256>>>(in, out);
    k_channel<<<OC_N / 8, 256>>>(out);
}

// round 8
// speedup vs baseline: 1.3065x; 1.1129x over previous
#include <cuda_runtime.h>

// Tensor: (1024, 1024, 3, 3) fp32
#define OC_N    1024
#define IC_N    1024
#define ROWS_N  (OC_N * IC_N)        // 1048576 kernel rows of 9
#define N_TOT   (ROWS_N * 9)         // 9437184
#define N_VEC4  (N_TOT / 4)          // 2359296
#define MAX_GRID 2304                // 2304*256 threads * 4 float4 = N_VEC4

__device__ float g_part_max[MAX_GRID];
__device__ float g_scale;
__device__ float g_rcp;

// ---------------------------------------------------------------------------
// Pass A: per-block max|t| partials.
__global__ void __launch_bounds__(256) k_maxabs(const float4* __restrict__ in) {
    const int base = blockIdx.x * 256 + threadIdx.x;
    const int stride = MAX_GRID * 256;
    float m = 0.0f;
#pragma unroll
    for (int k = 0; k < 4; k++) {
        float4 v = in[base + k * stride];
        m = fmaxf(m, fmaxf(fmaxf(fabsf(v.x), fabsf(v.y)),
                           fmaxf(fabsf(v.z), fabsf(v.w))));
    }
#pragma unroll
    for (int o = 16; o > 0; o >>= 1)
        m = fmaxf(m, __shfl_xor_sync(0xFFFFFFFFu, m, o));
    __shared__ float sm[8];
    if ((threadIdx.x & 31) == 0) sm[threadIdx.x >> 5] = m;
    __syncthreads();
    if (threadIdx.x == 0) {
        m = sm[0];
#pragma unroll
        for (int i = 1; i < 8; i++) m = fmaxf(m, sm[i]);
        g_part_max[blockIdx.x] = m;
    }
}

// ---------------------------------------------------------------------------
// Final max reduce + scale = max/127 (IEEE) + correctly-rounded reciprocal.
__global__ void __launch_bounds__(256) k_prep() {
    float m = 0.0f;
    for (int i = threadIdx.x; i < MAX_GRID; i += 256)
        m = fmaxf(m, g_part_max[i]);
#pragma unroll
    for (int o = 16; o > 0; o >>= 1)
        m = fmaxf(m, __shfl_xor_sync(0xFFFFFFFFu, m, o));
    __shared__ float sm[8];
    if ((threadIdx.x & 31) == 0) sm[threadIdx.x >> 5] = m;
    __syncthreads();
    if (threadIdx.x == 0) {
        m = sm[0];
#pragma unroll
        for (int i = 1; i < 8; i++) m = fmaxf(m, sm[i]);
        float s = __fdiv_rn(m, 127.0f);
        g_scale = s;
        g_rcp   = __frcp_rn(s);
    }
}

// ---------------------------------------------------------------------------
// Fused pass: one block = one OC channel (1024 rows of 9 = 9216 elems).
// Phase 1: per-row SQuant (4 rows/thread, interleaved rows -> 9-stride LDS is
//          conflict-free, gcd(9,32)=1), rn written back into the smem tile.
// Phase 2: block residual reduce -> channel nf/direction.
// Phase 3: histogram top-nf selection over the <=1024 boundary candidates,
//          patches applied DIRECTLY to the smem tile (disjoint elements).
// Phase 4: single scaled write-out. No candidate/residual global traffic.
__global__ void __launch_bounds__(256) k_main(const float* __restrict__ in,
                                              float* __restrict__ out) {
    __shared__ __align__(16) float tile[9216];   // 36 KB
    __shared__ unsigned skey[1024];
    __shared__ unsigned shist[256];
    __shared__ float    swred[8];
    __shared__ int      s_B;
    __shared__ unsigned s_c1;

    const int tid = threadIdx.x;
    const float scl = g_scale;                   // broadcast LDG
    const float rcp = g_rcp;

    const float4* in4 = reinterpret_cast<const float4*>(in)
                        + (size_t)blockIdx.x * 2304;
    float4* t4 = reinterpret_cast<float4*>(tile);
#pragma unroll
    for (int i = tid; i < 2304; i += 256) t4[i] = in4[i];
    shist[tid] = 0u;
    __syncthreads();

    // ---- Phase 1: 4 rows per thread (rows q*256+tid) ----
    float resid4 = 0.0f;
    unsigned mykey[4];
#pragma unroll
    for (int q = 0; q < 4; q++) {
        const int rbase = q * 2304 + tid * 9;    // = (q*256+tid)*9
        float rn[9], re[9], p[9];
        float esum = 0.0f;
#pragma unroll
        for (int i = 0; i < 9; i++) {
            float t  = tile[rbase + i];
            float q0 = __fmul_rn(t, rcp);                          // Markstein
            float x  = __fmaf_rn(__fmaf_rn(-scl, q0, t), rcp, q0); // == t/scl
            x = fminf(fmaxf(x, -127.0f), 127.0f);
            float r = rintf(x);        // round-half-to-even == jnp.round
            rn[i] = r;
            re[i] = __fadd_rn(r, -x);
            esum  = __fadd_rn(esum, re[i]);
        }
        const int   nf = (int)rintf(fabsf(esum));
        const bool  up = (esum < 0.0f);
        const float d1 = up ? 1.0f : -1.0f;
#pragma unroll
        for (int i = 0; i < 9; i++) {
            float c = up ? -re[i] : re[i];
            p[i] = fmaxf(c, 0.0f);
        }
        // pairwise stable rank (tie -> lower index outranks)
        int rank[9];
#pragma unroll
        for (int j = 0; j < 9; j++) rank[j] = j;
#pragma unroll
        for (int i = 0; i < 8; i++)
#pragma unroll
            for (int j = i + 1; j < 9; j++) {
                int gg = (int)(p[j] > p[i]);
                rank[i] += gg;
                rank[j] -= gg;
            }
        int bi = -1;
#pragma unroll
        for (int i = 0; i < 9; i++) {
            if (rank[i] < nf)      rn[i] += d1;
            if (rank[i] == nf - 1) bi = i;       // boundary element
            tile[rbase + i] = rn[i];             // own slots only
        }
        resid4 = __fadd_rn(resid4, __fmaf_rn((float)nf, d1, esum));

        // 32-bit candidate key: dir(1) | prio17 | (9216-elemFlat)(14)
        unsigned cand = 0u;
        if (bi >= 0) {
            float re2 = __fadd_rn(re[bi], d1);   // |re2| in [0.5,1): exp fixed
            int elemFlat = rbase + bi;           // already row*9+bi within OC
            unsigned mant = __float_as_uint(fabsf(re2)) & 0x7FFFFFu;
            cand = ((up ? 1u : 0u) << 31) | ((mant >> 6) << 14)
                 | (unsigned)(9216 - elemFlat);
        }
        mykey[q] = cand;
    }

    // ---- Phase 2: block residual reduce (fixed, deterministic order) ----
#pragma unroll
    for (int o = 16; o > 0; o >>= 1)
        resid4 += __shfl_xor_sync(0xFFFFFFFFu, resid4, o);
    if ((tid & 31) == 0) swred[tid >> 5] = resid4;
    __syncthreads();
    float esum_c = swred[0];
#pragma unroll
    for (int i = 1; i < 8; i++) esum_c = __fadd_rn(esum_c, swred[i]);
    const int nfc = (int)rintf(fabsf(esum_c));   // uniform across block

    if (nfc != 0) {
        const bool upc = (esum_c < 0.0f);
        // stage-2 up-flip reverts a stage-1 DOWN-flipped boundary (dir bit 0)
        const unsigned want   = upc ? 0u : 1u;
        const float    dpatch = upc ? 1.0f : -1.0f;   // pre-scale units

        // ---- Phase 3a: filter + histogram on key top-8-bits ----
#pragma unroll
        for (int q = 0; q < 4; q++) {
            unsigned k  = mykey[q];
            unsigned kk = (k != 0u && (k >> 31) == want) ? (k & 0x7FFFFFFFu)
                                                         : 0u;
            skey[q * 256 + tid] = kk;
            if (kk != 0u) atomicAdd(&shist[kk >> 23], 1u);
        }
        __syncthreads();

        // ---- Phase 3b: warp 0 suffix-scan -> threshold bucket B, c1 ----
        if (tid < 32) {
            const int lane = tid;
            const int g = 31 - lane;             // lane owns buckets 8g..8g+7
            unsigned s = 0u;
#pragma unroll
            for (int b = 0; b < 8; b++) s += shist[g * 8 + b];
            unsigned C = s;
#pragma unroll
            for (int o = 1; o < 32; o <<= 1) {
                unsigned v = __shfl_up_sync(0xFFFFFFFFu, C, o);
                if (lane >= o) C += v;
            }
            const unsigned ball = __ballot_sync(0xFFFFFFFFu,
                                                C >= (unsigned)nfc);
            const int lsel = (ball == 0u) ? 31 : (__ffs(ball) - 1);
            const unsigned Cl = __shfl_sync(0xFFFFFFFFu, C, lsel);
            const unsigned sl = __shfl_sync(0xFFFFFFFFu, s, lsel);
            const int gsel = 31 - lsel;
            unsigned hb[8];
#pragma unroll
            for (int b = 0; b < 8; b++) hb[b] = shist[gsel * 8 + b];
            int B = gsel * 8;
            unsigned c1 = Cl - sl;
            bool found = false;
#pragma unroll
            for (int b = 7; b >= 1; b--) {
                if (!found) {
                    if (c1 + hb[b] >= (unsigned)nfc) {
                        B = gsel * 8 + b; found = true;
                    } else c1 += hb[b];
                }
            }
            if (lane == 0) { s_B = B; s_c1 = c1; }
        }
        __syncthreads();
        const int      B  = s_B;
        const unsigned c1 = s_c1;

        // ---- Phase 3c: patch buckets > B directly in tile; keep bucket B ----
#pragma unroll
        for (int q = 0; q < 4; q++) {
            unsigned kk = skey[q * 256 + tid];
            if (kk != 0u && (kk >> 23) > (unsigned)B)
                tile[9216 - (int)(kk & 0x3FFFu)] += dpatch;  // disjoint elems
            skey[q * 256 + tid] =
                (kk != 0u && (kk >> 23) == (unsigned)B) ? kk : 0u;
        }
        __syncthreads();

        // ---- Phase 3d: warp 0 serial pick loop for k2 = nfc-c1 (tiny) ----
        if (tid < 32) {
            const int lane = tid;
            const int k2 = nfc - (int)c1;        // >= 1 by construction
            unsigned key[32];
#pragma unroll
            for (int j = 0; j < 32; j++) key[j] = skey[j * 32 + lane];
            unsigned lmax;
            {
                unsigned t[32];
#pragma unroll
                for (int j = 0; j < 32; j++) t[j] = key[j];
#pragma unroll
                for (int st = 16; st > 0; st >>= 1)
#pragma unroll
                    for (int j = 0; j < 16; j++)
                        if (j < st) t[j] = umax(t[j], t[j + st]);
                lmax = t[0];
            }
            for (int it = 0; it < k2; it++) {
                const unsigned m = __reduce_max_sync(0xFFFFFFFFu, lmax);
                if (m == 0u) break;              // exhausted (safe clamp)
                if (lane == 0)
                    tile[9216 - (int)(m & 0x3FFFu)] += dpatch;
                unsigned t[32];
#pragma unroll
                for (int j = 0; j < 32; j++) t[j] = (key[j] < m) ? key[j] : 0u;
#pragma unroll
                for (int st = 16; st > 0; st >>= 1)
#pragma unroll
                    for (int j = 0; j < 16; j++)
                        if (j < st) t[j] = umax(t[j], t[j + st]);
                lmax = t[0];
            }
        }
        __syncthreads();
    } else {
        __syncthreads();   // keep barrier count uniform (uniform branch anyway)
    }

    // ---- Phase 4: single scaled write-out ----
    float4* out4 = reinterpret_cast<float4*>(out) + (size_t)blockIdx.x * 2304;
#pragma unroll
    for (int i = tid; i < 2304; i += 256) {
        float4 v = t4[i];
        v.x = __fmul_rn(v.x, scl); v.y = __fmul_rn(v.y, scl);
        v.z = __fmul_rn(v.z, scl); v.w = __fmul_rn(v.w, scl);
        out4[i] = v;
    }
}

// ---------------------------------------------------------------------------
extern "C" void kernel_launch(void* const* d_in, const int* in_sizes, int n_in,
                              void* d_out, int out_size) {
    const float* in  = (const float*)d_in[0];
    float*       out = (float*)d_out;

    k_maxabs<<<MAX_GRID, 256>>>((const float4*)in);
    k_prep<<<1, 256>>>();
    k_main<<<OC_N, 256>>>(in, out);
}